// round 6
// baseline (speedup 1.0000x reference)
#include <cuda_runtime.h>
#include <math.h>

#define B 8
#define C 64
#define L 2048
#define CS 256
#define HD 64
#define TD 16
#define HH 32
#define FL 8
#define NT 25
#define NTOT (B*CS*L)          // 4,194,304
#define NCL  (B*C*L)           // 1,048,576

typedef unsigned long long ull;

// ---------------- scratch (device globals; no allocs allowed) ----------------
__device__ float g_stacked[NTOT];
__device__ float g_y[NTOT];
__device__ float g_ytmp[NTOT];
__device__ float g_s[6][NTOT];
__device__ float g_h1[B*HD*L];
__device__ float g_h2[B*HD*L];
__device__ float g_apA[NCL];
__device__ float g_apB[NCL];
__device__ float g_maxv[B*C];
__device__ float g_lof[FL], g_hif[FL];
__device__ float g_gamma[NT*HD], g_beta[NT*HD];
__device__ float g_part[B*64];

__device__ __forceinline__ float gelu(float x){
    return 0.5f * x * (1.0f + erff(x * 0.70710678118654752440f));
}

// ---------------- packed f32x2 helpers (sm_103a FFMA2) ----------------
__device__ __forceinline__ ull ffma2(ull a, ull b, ull c){
    ull d;
    asm("fma.rn.f32x2 %0, %1, %2, %3;" : "=l"(d) : "l"(a), "l"(b), "l"(c));
    return d;
}
__device__ __forceinline__ ull pack2(float lo, float hi){
    ull d;
    asm("mov.b64 %0, {%1, %2};" : "=l"(d) : "f"(lo), "f"(hi));
    return d;
}
__device__ __forceinline__ void unpack2(ull v, float& lo, float& hi){
    asm("mov.b64 {%0, %1}, %2;" : "=f"(lo), "=f"(hi) : "l"(v));
}

// ---------------- fused RK combine args ----------------
struct CombArgs {
    const float4* ybase;
    float4*       yout;
    const float4* sp[4];
    float         cp[4];
    float         cself;
    int           np;
};

// ---------------- tiled conv1d (k=3, pad=1), FFMA2 inner loop ----------------
// Grid: (L/128, B, OTOT/64). Block 256. Tile: 64 out-ch x 128 l.
// Thread: 4 o x 8 l. smem: x tile [64][132] + w chunk [192][68] (o-contiguous).
template<int IC, int OTOT, bool FILM, bool GELU_OUT, bool COMBINE>
__global__ void __launch_bounds__(256) conv_k(
    const float* __restrict__ in, const float* __restrict__ w,
    const float* __restrict__ bias, float* __restrict__ out,
    const float* __restrict__ gamma, const float* __restrict__ beta,
    CombArgs ca)
{
    extern __shared__ float smem[];
    float* sx = smem;                 // 64*132
    float* sw = smem + 64*132;        // 192*68

    const int tid = threadIdx.x;
    const int l0  = blockIdx.x * 128;
    const int b   = blockIdx.y;
    const int o0  = blockIdx.z * 64;
    const int lg  = tid & 15;
    const int og  = tid >> 4;
    const int lbase  = lg * 8;
    const int olocal = og * 4;

    ull acc[4][4];
    #pragma unroll
    for (int a = 0; a < 4; a++)
        #pragma unroll
        for (int q = 0; q < 4; q++) acc[a][q] = 0ULL;

    for (int ic0 = 0; ic0 < IC; ic0 += 64) {
        __syncthreads();
        // stage x tile [64][132]: j -> global l0-1+j, zero-pad ends + tail
        const float* inb = in + ((size_t)b * IC + ic0) * L;
        for (int idx = tid; idx < 64*132; idx += 256) {
            int ic = idx / 132, j = idx - ic*132;
            int gl = l0 - 1 + j;
            sx[idx] = (j < 130 && gl >= 0 && gl < L) ? inb[ic*L + gl] : 0.0f;
        }
        // stage weights: coalesced global read, o-contiguous smem (stride 68)
        const float* wb = w + ((size_t)o0 * IC + ic0) * 3;
        for (int idx = tid; idx < 64*192; idx += 256) {
            int o = idx / 192, r = idx - o*192;   // r = ic*3 + k
            sw[r*68 + o] = wb[(size_t)o * IC * 3 + r];
        }
        __syncthreads();

        #pragma unroll 2
        for (int ic = 0; ic < 64; ic++) {
            const float4* xr = (const float4*)(sx + ic*132 + lbase);
            float4 xa = xr[0], xb4 = xr[1], xc = xr[2];
            float xs[12] = {xa.x,xa.y,xa.z,xa.w, xb4.x,xb4.y,xb4.z,xb4.w,
                            xc.x,xc.y,xc.z,xc.w};
            ull xp[9];
            #pragma unroll
            for (int i = 0; i < 9; i++) xp[i] = pack2(xs[i], xs[i+1]);
            ull wp[3][4];
            #pragma unroll
            for (int k = 0; k < 3; k++) {
                float4 wv = *(const float4*)(sw + (ic*3 + k)*68 + olocal);
                wp[k][0] = pack2(wv.x, wv.x);
                wp[k][1] = pack2(wv.y, wv.y);
                wp[k][2] = pack2(wv.z, wv.z);
                wp[k][3] = pack2(wv.w, wv.w);
            }
            #pragma unroll
            for (int oo = 0; oo < 4; oo++)
                #pragma unroll
                for (int q = 0; q < 4; q++) {
                    acc[oo][q] = ffma2(wp[0][oo], xp[2*q],   acc[oo][q]);
                    acc[oo][q] = ffma2(wp[1][oo], xp[2*q+1], acc[oo][q]);
                    acc[oo][q] = ffma2(wp[2][oo], xp[2*q+2], acc[oo][q]);
                }
        }
    }

    // epilogue: bias (+FiLM)(+GELU) (+fused RK combine)
    #pragma unroll
    for (int oo = 0; oo < 4; oo++) {
        int o = o0 + olocal + oo;
        float bs = bias[o];
        float ga = 0.f, be = 0.f;
        if (FILM) { ga = gamma[o]; be = beta[o]; }
        float v[8];
        #pragma unroll
        for (int q = 0; q < 4; q++) unpack2(acc[oo][q], v[2*q], v[2*q+1]);
        #pragma unroll
        for (int j = 0; j < 8; j++) {
            float t = v[j] + bs;
            if (FILM)     t = (1.0f + ga) * t + be;
            if (GELU_OUT) t = gelu(t);
            v[j] = t;
        }
        size_t base = ((size_t)b * OTOT + o) * L + l0 + lbase;
        *(float4*)(out + base)     = make_float4(v[0],v[1],v[2],v[3]);
        *(float4*)(out + base + 4) = make_float4(v[4],v[5],v[6],v[7]);
        if (COMBINE) {
            size_t fi = base >> 2;
            #pragma unroll
            for (int g = 0; g < 2; g++) {
                float4 a = ca.ybase[fi + g];
                const float* vv = v + 4*g;
                a.x += ca.cself*vv[0]; a.y += ca.cself*vv[1];
                a.z += ca.cself*vv[2]; a.w += ca.cself*vv[3];
                for (int m = 0; m < ca.np; m++) {
                    float4 sv = ca.sp[m][fi + g];
                    float cm = ca.cp[m];
                    a.x += cm*sv.x; a.y += cm*sv.y; a.z += cm*sv.z; a.w += cm*sv.w;
                }
                ca.yout[fi + g] = a;
            }
        }
    }
}

// ---------------- time embedding: all 25 (gamma,beta) pairs ----------------
__global__ void temb_k(const float* __restrict__ tw1, const float* __restrict__ tb1,
                       const float* __restrict__ tw2, const float* __restrict__ tb2,
                       const float* __restrict__ cw,  const float* __restrict__ cb)
{
    int idx = blockIdx.x;       // 0..24
    int j = threadIdx.x;        // 0..127
    float t;
    if (idx == 24) t = 1.0f;
    else {
        const float off[6] = {0.0f, 0.2f, 0.3f, 0.8f, 8.0f/9.0f, 1.0f};
        t = (idx / 6) * 0.25f + off[idx % 6] * 0.25f;
    }
    __shared__ float e1[TD], te[TD];
    if (j < TD) e1[j] = gelu(t * tw1[j] + tb1[j]);
    __syncthreads();
    if (j < TD) {
        float s = tb2[j];
        for (int e = 0; e < TD; e++) s += e1[e] * tw2[j*TD + e];
        te[j] = s;
    }
    __syncthreads();
    float s = cb[j];
    for (int d = 0; d < TD; d++) s += te[d] * cw[j*TD + d];
    if (j < HD) g_gamma[idx*HD + j] = s;
    else        g_beta[idx*HD + (j - HD)] = s;
}

// ---------------- max over L per (b,c) (only needed for x) ----------------
__global__ void maxred_k(const float* __restrict__ in)
{
    int bc = blockIdx.x;
    const float* p = in + (size_t)bc * L;
    float m = -INFINITY;
    for (int i = threadIdx.x; i < L; i += 256) m = fmaxf(m, p[i]);
    __shared__ float sm[8];
    #pragma unroll
    for (int o = 16; o > 0; o >>= 1) m = fmaxf(m, __shfl_xor_sync(0xffffffffu, m, o));
    if ((threadIdx.x & 31) == 0) sm[threadIdx.x >> 5] = m;
    __syncthreads();
    if (threadIdx.x == 0) {
        float r = sm[0];
        for (int w = 1; w < 8; w++) r = fmaxf(r, sm[w]);
        g_maxv[bc] = r;
    }
}

// ---------------- dywan MLP -> normalized filters (weights staged in smem) ---
__global__ void dywan_k(const float* __restrict__ sw1, const float* __restrict__ sb1,
                        const float* __restrict__ sw2, const float* __restrict__ sb2,
                        const float* __restrict__ sw3, const float* __restrict__ sb3)
{
    __shared__ float s_w1[HH*C], s_w2[HH*HH], s_w3[16*HH], s_mx[B*C];
    __shared__ float feat[B*HH], g2[B*HH], raw[B*16], nrm[B*2];
    int tid = threadIdx.x;
    for (int i = tid; i < HH*C;  i += 256) s_w1[i] = sw1[i];
    for (int i = tid; i < HH*HH; i += 256) s_w2[i] = sw2[i];
    for (int i = tid; i < 16*HH; i += 256) s_w3[i] = sw3[i];
    for (int i = tid; i < B*C;   i += 256) s_mx[i] = g_maxv[i];
    __syncthreads();
    if (tid < B*HH) {
        int b = tid / HH, h = tid % HH;
        float s = sb1[h];
        #pragma unroll 8
        for (int c = 0; c < C; c++) s += s_mx[b*C + c] * s_w1[h*C + c];
        feat[tid] = gelu(s);
    }
    __syncthreads();
    if (tid < B*HH) {
        int b = tid / HH, h = tid % HH;
        float s = sb2[h];
        #pragma unroll 8
        for (int e = 0; e < HH; e++) s += feat[b*HH + e] * s_w2[h*HH + e];
        g2[tid] = gelu(s);
    }
    __syncthreads();
    if (tid < B*16) {
        int b = tid / 16, jj = tid % 16;
        float s = sb3[jj];
        #pragma unroll 8
        for (int e = 0; e < HH; e++) s += g2[b*HH + e] * s_w3[jj*HH + e];
        raw[tid] = s;
    }
    __syncthreads();
    if (tid < B*2) {
        int b = tid / 2, half = tid % 2;
        float s = 0.f;
        #pragma unroll
        for (int k = 0; k < FL; k++) { float v = raw[b*16 + half*8 + k]; s += v*v; }
        nrm[tid] = 1.0f / sqrtf(s);
    }
    __syncthreads();
    if (tid < 16) {
        int half = tid / 8, k = tid % 8;
        float s = 0.f;
        for (int b = 0; b < B; b++) s += raw[b*16 + half*8 + k] * nrm[b*2 + half];
        s *= (1.0f / B);
        if (half == 0) g_lof[k] = s; else g_hif[k] = s;
    }
}

// ---------------- depthwise wavelet conv + fused row-max for next level ------
// Grid: B*C blocks (one per (b,c) row), 256 threads.
__global__ void wconv_k(const float* __restrict__ in, float* __restrict__ newap,
                        int lev, int doMax)
{
    int bc = blockIdx.x;
    int b = bc / C, c = bc % C;
    const float* ap = in + (size_t)bc * L;
    size_t hoff = (size_t)b*CS*L + ((size_t)(lev+1)*C + c)*L;
    float* na = newap + (size_t)bc * L;
    float mx = -INFINITY;
    for (int l = threadIdx.x; l < L; l += 256) {
        float lo = 0.f, hi = 0.f;
        #pragma unroll
        for (int k = 0; k < FL; k++) {
            int src = l + k - 3;
            src = src < 0 ? -src : (src >= L ? 2*L - 2 - src : src);
            float v = ap[src];
            lo += g_lof[k] * v;
            hi += g_hif[k] * v;
        }
        na[l] = lo;
        g_stacked[hoff + l] = hi;
        g_y[hoff + l] = hi;
        mx = fmaxf(mx, lo);
    }
    if (doMax) {
        __shared__ float sm[8];
        #pragma unroll
        for (int o = 16; o > 0; o >>= 1) mx = fmaxf(mx, __shfl_xor_sync(0xffffffffu, mx, o));
        if ((threadIdx.x & 31) == 0) sm[threadIdx.x >> 5] = mx;
        __syncthreads();
        if (threadIdx.x == 0) {
            float r = sm[0];
            for (int w = 1; w < 8; w++) r = fmaxf(r, sm[w]);
            g_maxv[bc] = r;
        }
    }
}

// ---------------- copy x into stacked[:,0:C] and y[:,0:C] ----------------
__global__ void cpx_k(const float* __restrict__ x)
{
    int idx = blockIdx.x * blockDim.x + threadIdx.x;
    if (idx >= NCL) return;
    int b = idx / (C*L);
    int r = idx % (C*L);
    float v = x[idx];
    g_stacked[(size_t)b*CS*L + r] = v;
    g_y[(size_t)b*CS*L + r] = v;
}

// ---------------- ecloss partial + final ----------------
__global__ void ecl1_k(const float* __restrict__ dx)
{
    int b = blockIdx.x / 64, part = blockIdx.x % 64;
    const int CH = CS*L/64;  // 8192
    const float* sp = g_stacked + (size_t)b*CS*L + (size_t)part*CH;
    const float* dp = dx        + (size_t)b*CS*L + (size_t)part*CH;
    float s = 0.f;
    for (int i = threadIdx.x; i < CH; i += 256) s += sp[i] * dp[i];
    __shared__ float sm[8];
    #pragma unroll
    for (int o = 16; o > 0; o >>= 1) s += __shfl_xor_sync(0xffffffffu, s, o);
    if ((threadIdx.x & 31) == 0) sm[threadIdx.x >> 5] = s;
    __syncthreads();
    if (threadIdx.x == 0) {
        float t = 0.f;
        for (int w = 0; w < 8; w++) t += sm[w];
        g_part[blockIdx.x] = t;
    }
}

__global__ void ecl2_k(float* __restrict__ out)
{
    __shared__ float inner[B];
    if (threadIdx.x < B) {
        float s = 0.f;
        for (int p = 0; p < 64; p++) s += g_part[threadIdx.x*64 + p];
        inner[threadIdx.x] = s;
    }
    __syncthreads();
    if (threadIdx.x == 0) {
        float e = 0.f;
        for (int b = 0; b < B; b++) e += inner[b] * inner[b];
        out[4*NCL] = e / (float)B;
    }
}

// ---------------- output permute ----------------
__global__ void perm_k(float* __restrict__ out)
{
    int idx = blockIdx.x * blockDim.x + threadIdx.x;
    if (idx >= 4*NCL) return;
    int g = idx / NCL;
    int r = idx % NCL;
    int b = r / (C*L);
    int cl = r % (C*L);
    int c = cl / L, l = cl % L;
    out[idx] = g_y[(size_t)b*CS*L + ((size_t)(g*C + c))*L + l];
}

// ---------------- host orchestration ----------------
extern "C" void kernel_launch(void* const* d_in, const int* in_sizes, int n_in,
                              void* d_out, int out_size)
{
    const float* x   = (const float*)d_in[0];
    const float* sw1 = (const float*)d_in[1];
    const float* sb1 = (const float*)d_in[2];
    const float* sw2 = (const float*)d_in[3];
    const float* sb2 = (const float*)d_in[4];
    const float* sw3 = (const float*)d_in[5];
    const float* sb3 = (const float*)d_in[6];
    const float* tw1 = (const float*)d_in[7];
    const float* tb1 = (const float*)d_in[8];
    const float* tw2 = (const float*)d_in[9];
    const float* tb2 = (const float*)d_in[10];
    const float* cw  = (const float*)d_in[11];
    const float* cb  = (const float*)d_in[12];
    const float* k1  = (const float*)d_in[13];
    const float* kb1 = (const float*)d_in[14];
    const float* k2  = (const float*)d_in[15];
    const float* kb2 = (const float*)d_in[16];
    const float* k3  = (const float*)d_in[17];
    const float* kb3 = (const float*)d_in[18];
    float* out = (float*)d_out;

    float *y, *ytmp, *sbase, *h1, *h2, *apA, *apB, *gam, *bet;
    cudaGetSymbolAddress((void**)&y,    g_y);
    cudaGetSymbolAddress((void**)&ytmp, g_ytmp);
    cudaGetSymbolAddress((void**)&sbase,g_s);
    cudaGetSymbolAddress((void**)&h1,   g_h1);
    cudaGetSymbolAddress((void**)&h2,   g_h2);
    cudaGetSymbolAddress((void**)&apA,  g_apA);
    cudaGetSymbolAddress((void**)&apB,  g_apB);
    cudaGetSymbolAddress((void**)&gam,  g_gamma);
    cudaGetSymbolAddress((void**)&bet,  g_beta);
    float* s[6];
    for (int i = 0; i < 6; i++) s[i] = sbase + (size_t)i * NTOT;

    const int SMEMB = (64*132 + 192*68) * sizeof(float);  // 86016
    cudaFuncSetAttribute(conv_k<CS,HD,true,true,false>,   cudaFuncAttributeMaxDynamicSharedMemorySize, SMEMB);
    cudaFuncSetAttribute(conv_k<HD,HD,false,true,false>,  cudaFuncAttributeMaxDynamicSharedMemorySize, SMEMB);
    cudaFuncSetAttribute(conv_k<HD,CS,false,false,true>,  cudaFuncAttributeMaxDynamicSharedMemorySize, SMEMB);
    cudaFuncSetAttribute(conv_k<HD,CS,false,false,false>, cudaFuncAttributeMaxDynamicSharedMemorySize, SMEMB);

    CombArgs zca = {};

    // ---- wavelet decomposition (also populates y) ----
    cpx_k<<<NCL/256, 256>>>(x);
    temb_k<<<NT, 128>>>(tw1, tb1, tw2, tb2, cw, cb);

    maxred_k<<<B*C, 256>>>(x);
    dywan_k<<<1, 256>>>(sw1, sb1, sw2, sb2, sw3, sb3);
    wconv_k<<<B*C, 256>>>(x, apA, 0, 1);

    dywan_k<<<1, 256>>>(sw1, sb1, sw2, sb2, sw3, sb3);
    wconv_k<<<B*C, 256>>>(apA, apB, 1, 1);

    dywan_k<<<1, 256>>>(sw1, sb1, sw2, sb2, sw3, sb3);
    wconv_k<<<B*C, 256>>>(apB, apA, 2, 0);

    // ---- ODE (Dormand-Prince, fixed step), combine fused into conv3 ----
    auto eval12 = [&](const float* ib, int tidx) {
        conv_k<CS,HD,true,true,false><<<dim3(16,B,1), 256, SMEMB>>>(ib, k1, kb1, h1, gam + tidx*HD, bet + tidx*HD, zca);
        conv_k<HD,HD,false,true,false><<<dim3(16,B,1), 256, SMEMB>>>(h1, k2, kb2, h2, nullptr, nullptr, zca);
    };

    const float hs = 0.25f;
    for (int i = 0; i < 4; i++) {
        int t0 = i * 6;
        CombArgs ca;

        // stage 1: s0; ytmp = y + h/5 * s0
        eval12(y, t0 + 0);
        ca = {}; ca.ybase = (const float4*)y; ca.yout = (float4*)ytmp;
        ca.np = 0; ca.cself = hs * 0.2f;
        conv_k<HD,CS,false,false,true><<<dim3(16,B,4), 256, SMEMB>>>(h2, k3, kb3, s[0], nullptr, nullptr, ca);

        // stage 2
        eval12(ytmp, t0 + 1);
        ca = {}; ca.ybase = (const float4*)y; ca.yout = (float4*)ytmp;
        ca.np = 1;
        ca.sp[0] = (const float4*)s[0]; ca.cp[0] = hs * (float)(3.0/40.0);
        ca.cself = hs * (float)(9.0/40.0);
        conv_k<HD,CS,false,false,true><<<dim3(16,B,4), 256, SMEMB>>>(h2, k3, kb3, s[1], nullptr, nullptr, ca);

        // stage 3
        eval12(ytmp, t0 + 2);
        ca = {}; ca.ybase = (const float4*)y; ca.yout = (float4*)ytmp;
        ca.np = 2;
        ca.sp[0] = (const float4*)s[0]; ca.cp[0] = hs * (float)(44.0/45.0);
        ca.sp[1] = (const float4*)s[1]; ca.cp[1] = hs * (float)(-56.0/15.0);
        ca.cself = hs * (float)(32.0/9.0);
        conv_k<HD,CS,false,false,true><<<dim3(16,B,4), 256, SMEMB>>>(h2, k3, kb3, s[2], nullptr, nullptr, ca);

        // stage 4
        eval12(ytmp, t0 + 3);
        ca = {}; ca.ybase = (const float4*)y; ca.yout = (float4*)ytmp;
        ca.np = 3;
        ca.sp[0] = (const float4*)s[0]; ca.cp[0] = hs * (float)(19372.0/6561.0);
        ca.sp[1] = (const float4*)s[1]; ca.cp[1] = hs * (float)(-25360.0/2187.0);
        ca.sp[2] = (const float4*)s[2]; ca.cp[2] = hs * (float)(64448.0/6561.0);
        ca.cself = hs * (float)(-212.0/729.0);
        conv_k<HD,CS,false,false,true><<<dim3(16,B,4), 256, SMEMB>>>(h2, k3, kb3, s[3], nullptr, nullptr, ca);

        // stage 5
        eval12(ytmp, t0 + 4);
        ca = {}; ca.ybase = (const float4*)y; ca.yout = (float4*)ytmp;
        ca.np = 4;
        ca.sp[0] = (const float4*)s[0]; ca.cp[0] = hs * (float)(9017.0/3168.0);
        ca.sp[1] = (const float4*)s[1]; ca.cp[1] = hs * (float)(-355.0/33.0);
        ca.sp[2] = (const float4*)s[2]; ca.cp[2] = hs * (float)(46732.0/5247.0);
        ca.sp[3] = (const float4*)s[3]; ca.cp[3] = hs * (float)(49.0/176.0);
        ca.cself = hs * (float)(-5103.0/18656.0);
        conv_k<HD,CS,false,false,true><<<dim3(16,B,4), 256, SMEMB>>>(h2, k3, kb3, s[4], nullptr, nullptr, ca);

        // stage 6: y update (in-place)
        eval12(ytmp, t0 + 5);
        ca = {}; ca.ybase = (const float4*)y; ca.yout = (float4*)y;
        ca.np = 4;
        ca.sp[0] = (const float4*)s[0]; ca.cp[0] = hs * (float)(35.0/384.0);
        ca.sp[1] = (const float4*)s[2]; ca.cp[1] = hs * (float)(500.0/1113.0);
        ca.sp[2] = (const float4*)s[3]; ca.cp[2] = hs * (float)(125.0/192.0);
        ca.sp[3] = (const float4*)s[4]; ca.cp[3] = hs * (float)(-2187.0/6784.0);
        ca.cself = hs * (float)(11.0/84.0);
        conv_k<HD,CS,false,false,true><<<dim3(16,B,4), 256, SMEMB>>>(h2, k3, kb3, s[5], nullptr, nullptr, ca);
    }

    // ---- final dx + ecloss + outputs ----
    eval12(y, 24);
    conv_k<HD,CS,false,false,false><<<dim3(16,B,4), 256, SMEMB>>>(h2, k3, kb3, s[0], nullptr, nullptr, zca);
    ecl1_k<<<B*64, 256>>>(s[0]);
    ecl2_k<<<1, 64>>>(out);
    perm_k<<<(4*NCL)/256, 256>>>(out);
}